// round 6
// baseline (speedup 1.0000x reference)
#include <cuda_runtime.h>
#include <cuda_fp16.h>
#include <cuda_fp8.h>

#define D 128
#define N_MAX 100000
#define A_MAX 4096
#define S_MAX 512
#define TEMP_INV 10.0f

// Scratch (allocation-free rule: __device__ globals)
__device__ uint4         g_x8[N_MAX * 8];  // normalized rows, fp8 e4m3, 128 B/row
__device__ unsigned char g_lab[N_MAX];     // labels 0..9
__device__ float         g_loss[A_MAX];
__device__ unsigned int  g_ctr;            // zero-init; self-resetting

__device__ __forceinline__ __half2 fp8x2_to_h2(unsigned short v) {
    __half2_raw r = __nv_cvt_fp8x2_to_halfraw2((__nv_fp8x2_storage_t)v, __NV_E4M3);
    return *reinterpret_cast<__half2*>(&r);
}
__device__ __forceinline__ unsigned short f2_to_fp8x2(float a, float b) {
    return (unsigned short)__nv_cvt_float2_to_fp8x2(make_float2(a, b),
                                                    __NV_SATFINITE, __NV_E4M3);
}

// ---------------------------------------------------------------------------
// Kernel 1: normalize rows -> fp8 e4m3, store labels. 4 rows per warp (MLP=4).
// ---------------------------------------------------------------------------
__global__ __launch_bounds__(256)
void prep_kernel(const float* __restrict__ x,
                 const int* __restrict__ y, int N) {
    int gw   = (blockIdx.x * blockDim.x + threadIdx.x) >> 5;
    int lane = threadIdx.x & 31;
    int base = gw * 4;
    if (base >= N) return;

    float4 v[4];
    float  s[4];
#pragma unroll
    for (int r = 0; r < 4; ++r) {
        int row = base + r;
        v[r] = (row < N) ? __ldg((const float4*)(x + (size_t)row * D) + lane)
                         : make_float4(1.f, 0.f, 0.f, 0.f);
        s[r] = v[r].x * v[r].x + v[r].y * v[r].y + v[r].z * v[r].z + v[r].w * v[r].w;
    }
#pragma unroll
    for (int o = 16; o > 0; o >>= 1) {
#pragma unroll
        for (int r = 0; r < 4; ++r)
            s[r] += __shfl_xor_sync(0xffffffffu, s[r], o);
    }
#pragma unroll
    for (int r = 0; r < 4; ++r) {
        int row = base + r;
        if (row < N) {
            float rn = rsqrtf(s[r]);
            unsigned int p = (unsigned int)f2_to_fp8x2(v[r].x * rn, v[r].y * rn)
                           | ((unsigned int)f2_to_fp8x2(v[r].z * rn, v[r].w * rn) << 16);
            ((unsigned int*)g_x8)[(size_t)row * 32 + lane] = p;
        }
    }
    if (lane < 4 && base + lane < N)
        g_lab[base + lane] = (unsigned char)__ldg(y + base + lane);
}

// ---------------------------------------------------------------------------
// Kernel 2: one block per anchor + fused deterministic final reduction.
// 8 warps; each warp: 64 samples, 4 at a time (8 lanes/sample, uint4=16 fp8).
// Row gathers use __ldcs (streaming, evict-first) so labels stay L1-resident.
// Anchor staged pre-scaled by TEMP_INV.
// ---------------------------------------------------------------------------
__global__ __launch_bounds__(256)
void loss_kernel(const int* __restrict__ anchors,
                 const int* __restrict__ sampled, int S,
                 float* __restrict__ out) {
    __shared__ __half2 af[64];       // anchor row * TEMP_INV as 64 half2
    __shared__ int     sidx[S_MAX];
    __shared__ float   s_num[8], s_den[8];
    __shared__ int     s_cnt[8];
    __shared__ int     s_done;
    __shared__ float   s_red[256];

    int a    = blockIdx.x;
    int tid  = threadIdx.x;
    int lane = tid & 31;
    int w    = tid >> 5;
    int hl   = lane & 7;             // lane within 8-group
    int sub  = lane >> 3;            // which of 4 samples

    int aidx = __ldg(anchors + a);

    if (tid < 32) {
        unsigned int u = ((const unsigned int*)g_x8)[(size_t)aidx * 32 + tid];
        __half2 t = __float2half2_rn(TEMP_INV);
        af[tid * 2]     = __hmul2(fp8x2_to_h2((unsigned short)(u & 0xffffu)), t);
        af[tid * 2 + 1] = __hmul2(fp8x2_to_h2((unsigned short)(u >> 16)), t);
    }
    for (int i = tid; i < S; i += blockDim.x)
        sidx[i] = __ldg(sampled + (size_t)a * S + i);
    __syncthreads();

    __half2 a0 = af[hl * 8 + 0], a1 = af[hl * 8 + 1];
    __half2 a2 = af[hl * 8 + 2], a3 = af[hl * 8 + 3];
    __half2 a4 = af[hl * 8 + 4], a5 = af[hl * 8 + 5];
    __half2 a6 = af[hl * 8 + 6], a7 = af[hl * 8 + 7];

    unsigned char ya = g_lab[aidx];
    float num = 0.f, den = 0.f;
    int   cnt = 0;

    int per = S >> 3;                // 64 samples per warp
    int s0  = w * per;
#pragma unroll 4
    for (int i = 0; i < per; i += 4) {
        int si = sidx[s0 + i + sub];
        uint4 v = __ldcs(&g_x8[(size_t)si * 8 + hl]);   // streaming gather
        __half2 acc;
        acc = __hmul2(a0, fp8x2_to_h2((unsigned short)(v.x & 0xffffu)));
        acc = __hfma2(a1, fp8x2_to_h2((unsigned short)(v.x >> 16)), acc);
        acc = __hfma2(a2, fp8x2_to_h2((unsigned short)(v.y & 0xffffu)), acc);
        acc = __hfma2(a3, fp8x2_to_h2((unsigned short)(v.y >> 16)), acc);
        acc = __hfma2(a4, fp8x2_to_h2((unsigned short)(v.z & 0xffffu)), acc);
        acc = __hfma2(a5, fp8x2_to_h2((unsigned short)(v.z >> 16)), acc);
        acc = __hfma2(a6, fp8x2_to_h2((unsigned short)(v.w & 0xffffu)), acc);
        acc = __hfma2(a7, fp8x2_to_h2((unsigned short)(v.w >> 16)), acc);
        float2 f = __half22float2(acc);
        float  p = f.x + f.y;
#pragma unroll
        for (int o = 4; o > 0; o >>= 1)
            p += __shfl_xor_sync(0xffffffffu, p, o);
        if (hl == 0) {
            float e = __expf(p);                 // TEMP_INV already folded in
            den += e;
            if (g_lab[si] == ya) { num += e; cnt++; }
        }
    }

    num += __shfl_xor_sync(0xffffffffu, num, 8);
    den += __shfl_xor_sync(0xffffffffu, den, 8);
    cnt += __shfl_xor_sync(0xffffffffu, cnt, 8);
    num += __shfl_xor_sync(0xffffffffu, num, 16);
    den += __shfl_xor_sync(0xffffffffu, den, 16);
    cnt += __shfl_xor_sync(0xffffffffu, cnt, 16);
    if (lane == 0) { s_num[w] = num; s_den[w] = den; s_cnt[w] = cnt; }
    __syncthreads();

    if (tid == 0) {
        float tn = 0.f, td = 0.f; int tc = 0;
#pragma unroll
        for (int i = 0; i < 8; ++i) { tn += s_num[i]; td += s_den[i]; tc += s_cnt[i]; }
        float loss = 0.f;
        if (tc > 0)
            loss = (logf(td) - logf(tn)) / (float)tc;   // = -log(num/den)/cnt
        g_loss[a] = loss;
        __threadfence();                         // make g_loss visible at L2
        unsigned int t = atomicAdd(&g_ctr, 1u);
        s_done = (t == gridDim.x - 1) ? 1 : 0;
    }
    __syncthreads();

    // Last block performs the final sum in fixed order -> bit-deterministic.
    if (s_done) {
        int A = gridDim.x;
        float s = 0.f;
        for (int i = tid; i < A; i += 256)
            s += __ldcg(&g_loss[i]);             // bypass L1 (cross-SM data)
        s_red[tid] = s;
        __syncthreads();
#pragma unroll
        for (int o = 128; o > 0; o >>= 1) {
            if (tid < o) s_red[tid] += s_red[tid + o];
            __syncthreads();
        }
        if (tid == 0) {
            out[0] = s_red[0];
            g_ctr  = 0;                          // reset for next graph replay
        }
    }
}

// ---------------------------------------------------------------------------
extern "C" void kernel_launch(void* const* d_in, const int* in_sizes, int n_in,
                              void* d_out, int out_size) {
    const float* x       = (const float*)d_in[0];
    const int*   y       = (const int*)d_in[1];
    const int*   anchors = (const int*)d_in[2];
    const int*   sampled = (const int*)d_in[3];
    float*       out     = (float*)d_out;

    int N = in_sizes[1];                 // 100000
    int A = in_sizes[2];                 // 4096
    int S = in_sizes[3] / A;             // 512

    // 1) normalize -> fp8 + labels (32 rows per 256-thread block)
    int rows_per_block = 32;
    int pblocks = (N + rows_per_block - 1) / rows_per_block;
    prep_kernel<<<pblocks, 256>>>(x, y, N);

    // 2) per-anchor loss + fused deterministic reduction
    loss_kernel<<<A, 256>>>(anchors, sampled, S, out);
}

// round 7
// speedup vs baseline: 1.0424x; 1.0424x over previous
#include <cuda_runtime.h>

#define D 128
#define N_MAX 100000
#define A_MAX 4096
#define S_MAX 512
#define TEMP_INV 10.0f
#define QS 300.0f          // int8 quantization scale for normalized features
#define KEXP (TEMP_INV / (QS * QS))

// Scratch (allocation-free rule: __device__ globals)
__device__ uint4         g_q8[N_MAX * 8];  // normalized rows, int8 x128, 128 B/row
__device__ unsigned char g_lab[N_MAX];     // labels 0..9
__device__ float         g_loss[A_MAX];
__device__ unsigned int  g_ctr;            // zero-init; self-resetting

__device__ __forceinline__ int q8(float v) {
    int q = __float2int_rn(v * QS);
    return max(-127, min(127, q));
}

// ---------------------------------------------------------------------------
// Kernel 1: normalize rows -> int8 (scale QS), store labels. 4 rows/warp.
// ---------------------------------------------------------------------------
__global__ __launch_bounds__(256)
void prep_kernel(const float* __restrict__ x,
                 const int* __restrict__ y, int N) {
    int gw   = (blockIdx.x * blockDim.x + threadIdx.x) >> 5;
    int lane = threadIdx.x & 31;
    int base = gw * 4;
    if (base >= N) return;

    float4 v[4];
    float  s[4];
#pragma unroll
    for (int r = 0; r < 4; ++r) {
        int row = base + r;
        v[r] = (row < N) ? __ldg((const float4*)(x + (size_t)row * D) + lane)
                         : make_float4(1.f, 0.f, 0.f, 0.f);
        s[r] = v[r].x * v[r].x + v[r].y * v[r].y + v[r].z * v[r].z + v[r].w * v[r].w;
    }
#pragma unroll
    for (int o = 16; o > 0; o >>= 1) {
#pragma unroll
        for (int r = 0; r < 4; ++r)
            s[r] += __shfl_xor_sync(0xffffffffu, s[r], o);
    }
#pragma unroll
    for (int r = 0; r < 4; ++r) {
        int row = base + r;
        if (row < N) {
            float rn = rsqrtf(s[r]);
            int q0 = q8(v[r].x * rn), q1 = q8(v[r].y * rn);
            int q2 = q8(v[r].z * rn), q3 = q8(v[r].w * rn);
            unsigned int p = (unsigned int)(q0 & 0xff)
                           | ((unsigned int)(q1 & 0xff) << 8)
                           | ((unsigned int)(q2 & 0xff) << 16)
                           | ((unsigned int)(q3 & 0xff) << 24);
            ((unsigned int*)g_q8)[(size_t)row * 32 + lane] = p;
        }
    }
    if (lane < 4 && base + lane < N)
        g_lab[base + lane] = (unsigned char)__ldg(y + base + lane);
}

// ---------------------------------------------------------------------------
// Kernel 2: one block per anchor + fused deterministic final reduction.
// 8 warps; each warp: 64 samples, 4 at a time. 8 lanes per sample,
// uint4 = 16 int8 per lane, 4x DP4A exact integer dot, 3-step int reduce.
// ---------------------------------------------------------------------------
__global__ __launch_bounds__(256)
void loss_kernel(const int* __restrict__ anchors,
                 const int* __restrict__ sampled, int S,
                 float* __restrict__ out) {
    __shared__ int   s_aq[32];       // anchor row, 32 x u32 (packed int8)
    __shared__ int   sidx[S_MAX];
    __shared__ float s_num[8], s_den[8];
    __shared__ int   s_cnt[8];
    __shared__ int   s_done;
    __shared__ float s_red[256];

    int a    = blockIdx.x;
    int tid  = threadIdx.x;
    int lane = tid & 31;
    int w    = tid >> 5;
    int hl   = lane & 7;             // lane within 8-group
    int sub  = lane >> 3;            // which of 4 samples

    int aidx = __ldg(anchors + a);

    if (tid < 32)
        s_aq[tid] = ((const int*)g_q8)[(size_t)aidx * 32 + tid];
    for (int i = tid; i < S; i += blockDim.x)
        sidx[i] = __ldg(sampled + (size_t)a * S + i);
    __syncthreads();

    // per-lane anchor slice: 16 consecutive dims = 4 packed ints
    int aq0 = s_aq[hl * 4 + 0], aq1 = s_aq[hl * 4 + 1];
    int aq2 = s_aq[hl * 4 + 2], aq3 = s_aq[hl * 4 + 3];

    unsigned char ya = g_lab[aidx];
    float num = 0.f, den = 0.f;
    int   cnt = 0;

    int per = S >> 3;                // 64 samples per warp
    int s0  = w * per;
#pragma unroll 4
    for (int i = 0; i < per; i += 4) {
        int si = sidx[s0 + i + sub];
        uint4 v = __ldg(&g_q8[(size_t)si * 8 + hl]);   // 16 int8, L1-cached
        int p;
        p = __dp4a((int)v.x, aq0, 0);
        p = __dp4a((int)v.y, aq1, p);
        p = __dp4a((int)v.z, aq2, p);
        p = __dp4a((int)v.w, aq3, p);
#pragma unroll
        for (int o = 4; o > 0; o >>= 1)
            p += __shfl_xor_sync(0xffffffffu, p, o);
        if (hl == 0) {
            float e = __expf((float)p * KEXP);
            den += e;
            if (g_lab[si] == ya) { num += e; cnt++; }
        }
    }

    num += __shfl_xor_sync(0xffffffffu, num, 8);
    den += __shfl_xor_sync(0xffffffffu, den, 8);
    cnt += __shfl_xor_sync(0xffffffffu, cnt, 8);
    num += __shfl_xor_sync(0xffffffffu, num, 16);
    den += __shfl_xor_sync(0xffffffffu, den, 16);
    cnt += __shfl_xor_sync(0xffffffffu, cnt, 16);
    if (lane == 0) { s_num[w] = num; s_den[w] = den; s_cnt[w] = cnt; }
    __syncthreads();

    if (tid == 0) {
        float tn = 0.f, td = 0.f; int tc = 0;
#pragma unroll
        for (int i = 0; i < 8; ++i) { tn += s_num[i]; td += s_den[i]; tc += s_cnt[i]; }
        float loss = 0.f;
        if (tc > 0)
            loss = (logf(td) - logf(tn)) / (float)tc;   // = -log(num/den)/cnt
        g_loss[a] = loss;
        __threadfence();                         // publish g_loss
        unsigned int t = atomicAdd(&g_ctr, 1u);
        s_done = (t == gridDim.x - 1) ? 1 : 0;
    }
    __syncthreads();

    // Last block sums in fixed order -> bit-deterministic.
    if (s_done) {
        int A = gridDim.x;
        float s = 0.f;
        for (int i = tid; i < A; i += 256)
            s += __ldcg(&g_loss[i]);             // bypass L1 (cross-SM data)
        s_red[tid] = s;
        __syncthreads();
#pragma unroll
        for (int o = 128; o > 0; o >>= 1) {
            if (tid < o) s_red[tid] += s_red[tid + o];
            __syncthreads();
        }
        if (tid == 0) {
            out[0] = s_red[0];
            g_ctr  = 0;                          // reset for next graph replay
        }
    }
}

// ---------------------------------------------------------------------------
extern "C" void kernel_launch(void* const* d_in, const int* in_sizes, int n_in,
                              void* d_out, int out_size) {
    const float* x       = (const float*)d_in[0];
    const int*   y       = (const int*)d_in[1];
    const int*   anchors = (const int*)d_in[2];
    const int*   sampled = (const int*)d_in[3];
    float*       out     = (float*)d_out;

    int N = in_sizes[1];                 // 100000
    int A = in_sizes[2];                 // 4096
    int S = in_sizes[3] / A;             // 512

    // 1) normalize -> int8 + labels (32 rows per 256-thread block)
    int rows_per_block = 32;
    int pblocks = (N + rows_per_block - 1) / rows_per_block;
    prep_kernel<<<pblocks, 256>>>(x, y, N);

    // 2) per-anchor loss + fused deterministic reduction
    loss_kernel<<<A, 256>>>(anchors, sampled, S, out);
}

// round 8
// speedup vs baseline: 1.0717x; 1.0281x over previous
#include <cuda_runtime.h>

#define D 128
#define N_MAX 100000
#define A_MAX 4096
#define S_MAX 512
#define TEMP_INV 10.0f
#define QS 300.0f          // int8 quantization scale for normalized features
// exp(p*TEMP_INV/QS^2) == 2^(p * KE2)
#define KE2 (TEMP_INV / (QS * QS) * 1.44269504088896f)

// Scratch (allocation-free rule: __device__ globals)
__device__ uint4         g_q8[N_MAX * 8];  // normalized rows, int8 x128, 128 B/row
__device__ unsigned char g_lab[N_MAX];     // labels 0..9
__device__ float         g_loss[A_MAX];
__device__ unsigned int  g_ctr;            // zero-init; self-resetting

__device__ __forceinline__ int q8(float v) {
    int q = __float2int_rn(v * QS);
    return max(-127, min(127, q));
}

// ---------------------------------------------------------------------------
// Kernel 1: normalize rows -> int8 (scale QS), store labels. 4 rows/warp.
// ---------------------------------------------------------------------------
__global__ __launch_bounds__(256)
void prep_kernel(const float* __restrict__ x,
                 const int* __restrict__ y, int N) {
    int gw   = (blockIdx.x * blockDim.x + threadIdx.x) >> 5;
    int lane = threadIdx.x & 31;
    int base = gw * 4;
    if (base >= N) return;

    float4 v[4];
    float  s[4];
#pragma unroll
    for (int r = 0; r < 4; ++r) {
        int row = base + r;
        v[r] = (row < N) ? __ldg((const float4*)(x + (size_t)row * D) + lane)
                         : make_float4(1.f, 0.f, 0.f, 0.f);
        s[r] = v[r].x * v[r].x + v[r].y * v[r].y + v[r].z * v[r].z + v[r].w * v[r].w;
    }
#pragma unroll
    for (int o = 16; o > 0; o >>= 1) {
#pragma unroll
        for (int r = 0; r < 4; ++r)
            s[r] += __shfl_xor_sync(0xffffffffu, s[r], o);
    }
#pragma unroll
    for (int r = 0; r < 4; ++r) {
        int row = base + r;
        if (row < N) {
            float rn = rsqrtf(s[r]);
            int q0 = q8(v[r].x * rn), q1 = q8(v[r].y * rn);
            int q2 = q8(v[r].z * rn), q3 = q8(v[r].w * rn);
            unsigned int p = (unsigned int)(q0 & 0xff)
                           | ((unsigned int)(q1 & 0xff) << 8)
                           | ((unsigned int)(q2 & 0xff) << 16)
                           | ((unsigned int)(q3 & 0xff) << 24);
            ((unsigned int*)g_q8)[(size_t)row * 32 + lane] = p;
        }
    }
    if (lane < 4 && base + lane < N)
        g_lab[base + lane] = (unsigned char)__ldg(y + base + lane);
}

// ---------------------------------------------------------------------------
// Kernel 2: one block per anchor + fused deterministic final reduction.
// 8 warps; each warp: 64 samples, 4 at a time. 8 lanes per sample,
// uint4 = 16 int8 per lane, 4x DP4A dot, 3-step xor reduce.
// BRANCHLESS body: every lane of an 8-group redundantly accumulates the same
// e/mask (exact /8 at the end) so ptxas can software-pipeline the loads.
// ---------------------------------------------------------------------------
__global__ __launch_bounds__(256, 7)
void loss_kernel(const int* __restrict__ anchors,
                 const int* __restrict__ sampled, int S,
                 float* __restrict__ out) {
    __shared__ int   s_aq[32];       // anchor row, 32 x u32 (packed int8)
    __shared__ int   sidx[S_MAX];
    __shared__ float s_num[8], s_den[8];
    __shared__ int   s_cnt[8];
    __shared__ int   s_done;
    __shared__ float s_red[256];

    int a    = blockIdx.x;
    int tid  = threadIdx.x;
    int lane = tid & 31;
    int w    = tid >> 5;
    int hl   = lane & 7;             // lane within 8-group
    int sub  = lane >> 3;            // which of 4 samples

    int aidx = __ldg(anchors + a);

    if (tid < 32)
        s_aq[tid] = ((const int*)g_q8)[(size_t)aidx * 32 + tid];
    for (int i = tid; i < S; i += blockDim.x)
        sidx[i] = __ldg(sampled + (size_t)a * S + i);
    __syncthreads();

    // per-lane anchor slice: 16 consecutive dims = 4 packed ints
    int aq0 = s_aq[hl * 4 + 0], aq1 = s_aq[hl * 4 + 1];
    int aq2 = s_aq[hl * 4 + 2], aq3 = s_aq[hl * 4 + 3];

    unsigned char ya = g_lab[aidx];
    float num = 0.f, den = 0.f;
    int   cnt = 0;

    int per = S >> 3;                // 64 samples per warp
    int s0  = w * per;
#pragma unroll 4
    for (int i = 0; i < per; i += 4) {
        int si = sidx[s0 + i + sub];
        uint4 v = __ldg(&g_q8[(size_t)si * 8 + hl]);   // 16 int8, coalesced
        int p;
        p = __dp4a((int)v.x, aq0, 0);
        p = __dp4a((int)v.y, aq1, p);
        p = __dp4a((int)v.z, aq2, p);
        p = __dp4a((int)v.w, aq3, p);
        p += __shfl_xor_sync(0xffffffffu, p, 4);
        p += __shfl_xor_sync(0xffffffffu, p, 2);
        p += __shfl_xor_sync(0xffffffffu, p, 1);
        float fp = (float)p * KE2;
        float e;
        asm("ex2.approx.ftz.f32 %0, %1;" : "=f"(e) : "f"(fp));
        bool pos = (g_lab[si] == ya);
        den += e;
        num += pos ? e : 0.f;
        cnt += (int)pos;
    }

    // full 32-lane reduce; each sample was counted 8x (once per group lane)
#pragma unroll
    for (int o = 16; o > 0; o >>= 1) {
        num += __shfl_xor_sync(0xffffffffu, num, o);
        den += __shfl_xor_sync(0xffffffffu, den, o);
        cnt += __shfl_xor_sync(0xffffffffu, cnt, o);
    }
    if (lane == 0) {
        s_num[w] = num * 0.125f;     // exact: /8
        s_den[w] = den * 0.125f;
        s_cnt[w] = cnt >> 3;
    }
    __syncthreads();

    if (tid == 0) {
        float tn = 0.f, td = 0.f; int tc = 0;
#pragma unroll
        for (int i = 0; i < 8; ++i) { tn += s_num[i]; td += s_den[i]; tc += s_cnt[i]; }
        float loss = 0.f;
        if (tc > 0)
            loss = (logf(td) - logf(tn)) / (float)tc;   // = -log(num/den)/cnt
        g_loss[a] = loss;
        __threadfence();                         // publish g_loss
        unsigned int t = atomicAdd(&g_ctr, 1u);
        s_done = (t == gridDim.x - 1) ? 1 : 0;
    }
    __syncthreads();

    // Last block sums in fixed order -> bit-deterministic.
    if (s_done) {
        int A = gridDim.x;
        float s = 0.f;
        for (int i = tid; i < A; i += 256)
            s += __ldcg(&g_loss[i]);             // bypass L1 (cross-SM data)
        s_red[tid] = s;
        __syncthreads();
#pragma unroll
        for (int o = 128; o > 0; o >>= 1) {
            if (tid < o) s_red[tid] += s_red[tid + o];
            __syncthreads();
        }
        if (tid == 0) {
            out[0] = s_red[0];
            g_ctr  = 0;                          // reset for next graph replay
        }
    }
}

// ---------------------------------------------------------------------------
extern "C" void kernel_launch(void* const* d_in, const int* in_sizes, int n_in,
                              void* d_out, int out_size) {
    const float* x       = (const float*)d_in[0];
    const int*   y       = (const int*)d_in[1];
    const int*   anchors = (const int*)d_in[2];
    const int*   sampled = (const int*)d_in[3];
    float*       out     = (float*)d_out;

    int N = in_sizes[1];                 // 100000
    int A = in_sizes[2];                 // 4096
    int S = in_sizes[3] / A;             // 512

    // 1) normalize -> int8 + labels (32 rows per 256-thread block)
    int rows_per_block = 32;
    int pblocks = (N + rows_per_block - 1) / rows_per_block;
    prep_kernel<<<pblocks, 256>>>(x, y, N);

    // 2) per-anchor loss + fused deterministic reduction
    loss_kernel<<<A, 256>>>(anchors, sampled, S, out);
}